// round 10
// baseline (speedup 1.0000x reference)
#include <cuda_runtime.h>
#include <cstdint>

#define N_POSN 8192
#define NB     4
#define NG     512
#define NJ     2048   /* NB*NG */
#define NREP   8
#define EPSF   1e-6f
#define GROWS  16                       /* rows per CTA */
#define GCTAS  (N_POSN / GROWS)         /* 512 */
#define GTHR   512

// ---------------- device scratch (allocation-free) ----------------
__device__ float g_Dg[(long long)N_POSN * NJ];   // 64MB compact gathered columns, [n][j]
__device__ float g_rowmin[NB * N_POSN];          // min_g D[n,g] per batch, [b][n]
__device__ float g_S8[NREP][NJ];                 // replicated sum_n 1/(w+eps)
__device__ float g_t1[NB];
__device__ float g_ne[NB];
__device__ int   g_maxbits;                      // atomicMax, idempotent across replays (dis>=0)
__device__ float g_pmin;
__device__ float g_pmax;

// ---------------- kernel 1: stream dis_matrix once (register prefetch, 512thr) ----------------
// Per row: issue next row's 4x LDG.128 into registers FIRST (DRAM latency hides
// behind the smem gather + compact store of the current row), gather, barrier,
// regs -> smem, barrier. 32KB static smem; gt indices in 4 regs/thread;
// ~40 regs -> 4 CTAs/SM (full warp occupancy), 128KB/SM of in-flight loads.
__global__ void __launch_bounds__(GTHR) k_gather(const float* __restrict__ dis,
                                                 const int* __restrict__ gt,
                                                 const float* __restrict__ pm) {
    __shared__ float srow[N_POSN];           // 32KB
    __shared__ int   sminw[2][NB][16];       // per-warp per-batch min bits (double-buffered)
    __shared__ int   spmin[16], spmax[16];
    const int tid = threadIdx.x;
    const int wid = tid >> 5;

    // each thread owns j = it*512 + tid  (it = batch index 0..3)
    int mycol[4];
    #pragma unroll
    for (int it = 0; it < 4; it++) mycol[it] = gt[it * GTHR + tid];

    const int n0 = blockIdx.x * GROWS;       // 512 CTAs x 16 rows
    float lmax = 0.0f;

    // prologue: row n0 -> srow (fold into max here)
    {
        const float4* src = reinterpret_cast<const float4*>(dis + (long long)n0 * N_POSN);
        float4* dst = reinterpret_cast<float4*>(srow);
        #pragma unroll
        for (int i = 0; i < 4; i++) {
            float4 v = __ldcs(src + i * GTHR + tid);
            lmax = fmaxf(lmax, fmaxf(fmaxf(v.x, v.y), fmaxf(v.z, v.w)));
            dst[i * GTHR + tid] = v;
        }
    }
    __syncthreads();

    for (int r = 0; r < GROWS; r++) {
        const int n = n0 + r;

        // 1) issue next row's loads NOW — they land while we gather below
        float4 v[4];
        if (r < GROWS - 1) {
            const float4* src = reinterpret_cast<const float4*>(dis + (long long)(n + 1) * N_POSN);
            #pragma unroll
            for (int i = 0; i < 4; i++) v[i] = __ldcs(src + i * GTHR + tid);
        }

        // 2) gather row n from srow -> compact Dg (coalesced); one val/batch/thread
        float* out = g_Dg + (long long)n * NJ;
        float lmin[4];
        #pragma unroll
        for (int it = 0; it < 4; it++) {
            float val = srow[mycol[it]];
            out[it * GTHR + tid] = val;
            lmin[it] = val;
        }

        // 3) per-batch rowmin: warp reduce -> sminw[r&1]
        #pragma unroll
        for (int b = 0; b < NB; b++) {
            float m = lmin[b];
            #pragma unroll
            for (int o = 16; o; o >>= 1)
                m = fminf(m, __shfl_xor_sync(0xFFFFFFFFu, m, o));
            if ((tid & 31) == 0) sminw[r & 1][b][wid] = __float_as_int(m);
        }
        __syncthreads();   // srow reads + sminw writes done

        // 4a) threads 0-3: finish rowmin reduce, plain store
        if (tid < NB) {
            int mb = sminw[r & 1][tid][0];
            #pragma unroll
            for (int w = 1; w < 16; w++) mb = min(mb, sminw[r & 1][tid][w]);
            g_rowmin[tid * N_POSN + n] = __int_as_float(mb);
        }
        // 4b) store prefetched row into srow + fold into max
        if (r < GROWS - 1) {
            float4* dst = reinterpret_cast<float4*>(srow);
            #pragma unroll
            for (int i = 0; i < 4; i++) {
                float4 w = v[i];
                lmax = fmaxf(lmax, fmaxf(fmaxf(w.x, w.y), fmaxf(w.z, w.w)));
                dst[i * GTHR + tid] = w;
            }
            __syncthreads();   // srow visible for next gather; sminw[r&1] safe at r+2
        }
    }

    #pragma unroll
    for (int o = 16; o; o >>= 1)
        lmax = fmaxf(lmax, __shfl_xor_sync(0xFFFFFFFFu, lmax, o));
    if ((tid & 31) == 0) atomicMax(&g_maxbits, __float_as_int(lmax));

    // ---- CTA 0 extra duties (ordered before k_main by the kernel boundary) ----
    if (blockIdx.x == 0) {
        float* s8 = &g_S8[0][0];
        for (int i = tid; i < NREP * NJ; i += GTHR) s8[i] = 0.0f;
        if (tid < NB) { g_t1[tid] = 0.0f; g_ne[tid] = 0.0f; }

        float mn = __int_as_float(0x7F7FFFFF);
        float mx = -__int_as_float(0x7F7FFFFF);
        const float4* pm4 = reinterpret_cast<const float4*>(pm);
        for (int i = tid; i < (NB * N_POSN) / 4; i += GTHR) {
            float4 v = pm4[i];
            mn = fminf(mn, fminf(fminf(v.x, v.y), fminf(v.z, v.w)));
            mx = fmaxf(mx, fmaxf(fmaxf(v.x, v.y), fmaxf(v.z, v.w)));
        }
        #pragma unroll
        for (int o = 16; o; o >>= 1) {
            mn = fminf(mn, __shfl_xor_sync(0xFFFFFFFFu, mn, o));
            mx = fmaxf(mx, __shfl_xor_sync(0xFFFFFFFFu, mx, o));
        }
        if ((tid & 31) == 0) { spmin[wid] = __float_as_int(mn); spmax[wid] = __float_as_int(mx); }
        __syncthreads();
        if (tid == 0) {
            int a = spmin[0], b = spmax[0];
            #pragma unroll
            for (int w = 1; w < 16; w++) { a = min(a, spmin[w]); b = max(b, spmax[w]); }
            g_pmin = __int_as_float(a);
            g_pmax = __int_as_float(b);
        }
    }
}

// ---------------- kernel 2: main reduction over compact Dg ----------------
// Thread tid owns 4 consecutive j, batch k = tid>>7; explicit 8-deep load batching.
#define B_ROWS 16
__global__ void __launch_bounds__(512) k_main(const float* __restrict__ pm) {
    const float maxd = __int_as_float(g_maxbits);
    const float pmin = g_pmin;
    const float invr = 1.0f / (g_pmax - pmin);
    const float c0   = maxd + EPSF;

    const int tid = threadIdx.x;
    const int k   = tid >> 7;
    const int n0  = blockIdx.x * B_ROWS;      // 512 CTAs

    float4 acc = make_float4(0.f, 0.f, 0.f, 0.f);
    const float4* Dg4 = reinterpret_cast<const float4*>(g_Dg);

    #pragma unroll
    for (int c = 0; c < B_ROWS / 8; c++) {
        float4 d[8];
        float  pv[8];
        #pragma unroll
        for (int i = 0; i < 8; i++)
            d[i] = Dg4[(long long)(n0 + c * 8 + i) * 512 + tid];
        #pragma unroll
        for (int i = 0; i < 8; i++)
            pv[i] = __ldg(pm + k * N_POSN + n0 + c * 8 + i);
        #pragma unroll
        for (int i = 0; i < 8; i++) {
            float p    = fminf(fmaxf((pv[i] - pmin) * invr, 0.0f), 1.0f);
            float base = fmaf(-p, maxd, c0);
            acc.x += __fdividef(1.0f, fmaf(p, d[i].x, base));
            acc.y += __fdividef(1.0f, fmaf(p, d[i].y, base));
            acc.z += __fdividef(1.0f, fmaf(p, d[i].z, base));
            acc.w += __fdividef(1.0f, fmaf(p, d[i].w, base));
        }
    }

    float* Srep = g_S8[blockIdx.x & (NREP - 1)];
    atomicAdd(&Srep[4 * tid + 0], acc.x);
    atomicAdd(&Srep[4 * tid + 1], acc.y);
    atomicAdd(&Srep[4 * tid + 2], acc.z);
    atomicAdd(&Srep[4 * tid + 3], acc.w);

    if (tid < 64) {
        const int b  = tid >> 4;
        const int n  = n0 + (tid & 15);
        float pmv = __ldg(pm + b * N_POSN + n);
        float p   = fminf(fmaxf((pmv - pmin) * invr, 0.0f), 1.0f);
        float rm  = g_rowmin[b * N_POSN + n];
        float t1  = p * rm;
        float ne  = p;
        #pragma unroll
        for (int o = 8; o; o >>= 1) {
            t1 += __shfl_xor_sync(0xFFFFFFFFu, t1, o);
            ne += __shfl_xor_sync(0xFFFFFFFFu, ne, o);
        }
        if ((tid & 15) == 0) {
            atomicAdd(&g_t1[b], t1);
            atomicAdd(&g_ne[b], ne);
        }
    }
}

// ---------------- kernel 3: finalize scalar ----------------
__global__ void __launch_bounds__(512) k_final(float* __restrict__ out) {
    __shared__ float ssum[512];
    const int tid = threadIdx.x;
    float s = 0.0f;
    #pragma unroll
    for (int m = 0; m < NJ / 512; m++) {
        int j = tid + m * 512;
        float S = 0.0f;
        #pragma unroll
        for (int rp = 0; rp < NREP; rp++) S += g_S8[rp][j];
        s += (float)N_POSN / S;
    }
    ssum[tid] = s;
    __syncthreads();
    for (int o = 256; o; o >>= 1) {
        if (tid < o) ssum[tid] += ssum[tid + o];
        __syncthreads();
    }
    if (tid == 0) {
        float term2 = ssum[0] / (float)(NB * NG);
        float term1 = 0.0f;
        #pragma unroll
        for (int b = 0; b < NB; b++)
            term1 += g_t1[b] / (g_ne[b] + EPSF);
        term1 *= (1.0f / NB);
        out[0] = term1 + term2;
    }
}

// ---------------- launch ----------------
extern "C" void kernel_launch(void* const* d_in, const int* in_sizes, int n_in,
                              void* d_out, int out_size) {
    (void)in_sizes; (void)n_in; (void)out_size;
    const float* prob_map = (const float*)d_in[0];   // (4, 8192) f32
    const int*   gt       = (const int*)d_in[1];     // (4, 512)  i32
    const float* dis      = (const float*)d_in[2];   // (8192, 8192) f32
    float* out = (float*)d_out;

    k_gather<<<GCTAS, GTHR>>>(dis, gt, prob_map);
    k_main<<<N_POSN / B_ROWS, 512>>>(prob_map);
    k_final<<<1, 512>>>(out);
}

// round 11
// speedup vs baseline: 1.0573x; 1.0573x over previous
#include <cuda_runtime.h>
#include <cuda_fp16.h>
#include <cstdint>

#define N_POSN 8192
#define NB     4
#define NG     512
#define NJ     2048   /* NB*NG */
#define NREP   8
#define EPSF   1e-6f

// ---------------- device scratch (allocation-free) ----------------
__device__ __half g_Dg16[(long long)N_POSN * NJ]; // 32MB compact gathered columns, [n][j], fp16
__device__ float  g_rowmin[NB * N_POSN];          // min_g D[n,g] per batch, [b][n] (fp32, exact)
__device__ float  g_S8[NREP][NJ];                 // replicated sum_n 1/(w+eps)
__device__ float  g_t1[NB];
__device__ float  g_ne[NB];
__device__ int    g_maxbits;                      // atomicMax, idempotent across replays (dis>=0)
__device__ float  g_pmin;
__device__ float  g_pmax;

// ---------------- kernel 1: stream dis_matrix once (R8 shape + fp16 Dg) ----------------
// 256 thr, 1024 CTAs x 8 rows. Per row: issue next row's 8x LDG.128 into regs
// FIRST (DRAM latency hides behind the gather), gather pairs from smem ->
// half2 compact store, rowmin via warp+smem reduce, barrier, regs->smem, barrier.
// gt indices live in 8 registers/thread (no per-row index LDS).
__global__ void __launch_bounds__(256) k_gather(const float* __restrict__ dis,
                                                const int* __restrict__ gt,
                                                const float* __restrict__ pm) {
    __shared__ float srow[N_POSN];           // 32KB
    __shared__ int   sminw[2][NB][8];        // per-warp per-batch min bits (double-buffered)
    __shared__ int   spmin[8], spmax[8];
    const int tid = threadIdx.x;
    const int wid = tid >> 5;

    // thread owns j = it*512 + 2*tid + {0,1}; batch = it
    int mycol[8];
    #pragma unroll
    for (int it = 0; it < 4; it++) {
        mycol[2 * it]     = gt[it * 512 + 2 * tid];
        mycol[2 * it + 1] = gt[it * 512 + 2 * tid + 1];
    }

    const int n0 = blockIdx.x * 8;           // 1024 CTAs x 8 rows
    float lmax = 0.0f;

    // prologue: row n0 -> srow
    {
        const float4* src = reinterpret_cast<const float4*>(dis + (long long)n0 * N_POSN);
        float4* dst = reinterpret_cast<float4*>(srow);
        #pragma unroll
        for (int i = 0; i < 8; i++) {
            float4 v = __ldcs(src + i * 256 + tid);
            lmax = fmaxf(lmax, fmaxf(fmaxf(v.x, v.y), fmaxf(v.z, v.w)));
            dst[i * 256 + tid] = v;
        }
    }
    __syncthreads();

    #pragma unroll
    for (int r = 0; r < 8; r++) {
        const int n = n0 + r;

        // 1) issue next row's loads NOW — they land while we gather below
        float4 v[8];
        if (r < 7) {
            const float4* src = reinterpret_cast<const float4*>(dis + (long long)(n + 1) * N_POSN);
            #pragma unroll
            for (int i = 0; i < 8; i++) v[i] = __ldcs(src + i * 256 + tid);
        }

        // 2) gather pairs from srow -> half2 compact store (coalesced)
        __half2* out2 = reinterpret_cast<__half2*>(g_Dg16 + (long long)n * NJ);
        float lmin[4];
        #pragma unroll
        for (int it = 0; it < 4; it++) {
            float a = srow[mycol[2 * it]];
            float b = srow[mycol[2 * it + 1]];
            out2[it * 256 + tid] = __floats2half2_rn(a, b);
            lmin[it] = fminf(a, b);
        }

        // 3) per-batch rowmin: warp reduce -> sminw[r&1]
        #pragma unroll
        for (int b = 0; b < NB; b++) {
            float m = lmin[b];
            #pragma unroll
            for (int o = 16; o; o >>= 1)
                m = fminf(m, __shfl_xor_sync(0xFFFFFFFFu, m, o));
            if ((tid & 31) == 0) sminw[r & 1][b][wid] = __float_as_int(m);
        }
        __syncthreads();   // srow reads + sminw writes done

        // 4a) threads 0-3: finish rowmin reduce, plain store (fp32 exact)
        if (tid < NB) {
            int mb = sminw[r & 1][tid][0];
            #pragma unroll
            for (int w = 1; w < 8; w++) mb = min(mb, sminw[r & 1][tid][w]);
            g_rowmin[tid * N_POSN + n] = __int_as_float(mb);
        }
        // 4b) store prefetched row into srow + fold into max
        if (r < 7) {
            float4* dst = reinterpret_cast<float4*>(srow);
            #pragma unroll
            for (int i = 0; i < 8; i++) {
                float4 w = v[i];
                lmax = fmaxf(lmax, fmaxf(fmaxf(w.x, w.y), fmaxf(w.z, w.w)));
                dst[i * 256 + tid] = w;
            }
            __syncthreads();   // srow visible; sminw[r&1] safe for reuse at r+2
        }
    }

    #pragma unroll
    for (int o = 16; o; o >>= 1)
        lmax = fmaxf(lmax, __shfl_xor_sync(0xFFFFFFFFu, lmax, o));
    if ((tid & 31) == 0) atomicMax(&g_maxbits, __float_as_int(lmax));

    // ---- CTA 0 extra duties (ordered before k_main by the kernel boundary) ----
    if (blockIdx.x == 0) {
        float* s8 = &g_S8[0][0];
        for (int i = tid; i < NREP * NJ; i += 256) s8[i] = 0.0f;
        if (tid < NB) { g_t1[tid] = 0.0f; g_ne[tid] = 0.0f; }

        float mn = __int_as_float(0x7F7FFFFF);
        float mx = -__int_as_float(0x7F7FFFFF);
        const float4* pm4 = reinterpret_cast<const float4*>(pm);
        for (int i = tid; i < (NB * N_POSN) / 4; i += 256) {
            float4 v = pm4[i];
            mn = fminf(mn, fminf(fminf(v.x, v.y), fminf(v.z, v.w)));
            mx = fmaxf(mx, fmaxf(fmaxf(v.x, v.y), fmaxf(v.z, v.w)));
        }
        #pragma unroll
        for (int o = 16; o; o >>= 1) {
            mn = fminf(mn, __shfl_xor_sync(0xFFFFFFFFu, mn, o));
            mx = fmaxf(mx, __shfl_xor_sync(0xFFFFFFFFu, mx, o));
        }
        if ((tid & 31) == 0) { spmin[wid] = __float_as_int(mn); spmax[wid] = __float_as_int(mx); }
        __syncthreads();
        if (tid == 0) {
            int a = spmin[0], b = spmax[0];
            #pragma unroll
            for (int w = 1; w < 8; w++) { a = min(a, spmin[w]); b = max(b, spmax[w]); }
            g_pmin = __int_as_float(a);
            g_pmax = __int_as_float(b);
        }
    }
}

// ---------------- kernel 2: main reduction over compact fp16 Dg ----------------
// 512 CTAs x 512 thr, 16 rows/CTA, 2 rows in flight (tid>>8 selects row parity).
// Thread owns 8 consecutive j = 8*(tid&255) .. +7 : one LDG.128 (8 halves) per row.
#define B_ROWS 16
__global__ void __launch_bounds__(512) k_main(const float* __restrict__ pm) {
    const float maxd = __int_as_float(g_maxbits);
    const float pmin = g_pmin;
    const float invr = 1.0f / (g_pmax - pmin);
    const float c0   = maxd + EPSF;

    const int tid   = threadIdx.x;
    const int rh    = tid >> 8;               // row parity (0/1)
    const int jj    = tid & 255;
    const int j0    = 8 * jj;                 // 8 consecutive j, all in batch k
    const int k     = jj >> 6;                // batch (warp-uniform)
    const int n0    = blockIdx.x * B_ROWS;    // 512 CTAs

    float acc[8];
    #pragma unroll
    for (int q = 0; q < 8; q++) acc[q] = 0.0f;

    uint4 d[8];
    float pv[8];
    #pragma unroll
    for (int i = 0; i < 8; i++) {
        const int n = n0 + 2 * i + rh;
        d[i] = *reinterpret_cast<const uint4*>(g_Dg16 + (long long)n * NJ + j0);
    }
    #pragma unroll
    for (int i = 0; i < 8; i++)
        pv[i] = __ldg(pm + k * N_POSN + n0 + 2 * i + rh);
    #pragma unroll
    for (int i = 0; i < 8; i++) {
        float p    = fminf(fmaxf((pv[i] - pmin) * invr, 0.0f), 1.0f);
        float base = fmaf(-p, maxd, c0);                   // (1-p)*maxd + eps
        const __half2* hp = reinterpret_cast<const __half2*>(&d[i]);
        #pragma unroll
        for (int q = 0; q < 4; q++) {
            float2 f = __half22float2(hp[q]);
            acc[2 * q]     += __fdividef(1.0f, fmaf(p, f.x, base));
            acc[2 * q + 1] += __fdividef(1.0f, fmaf(p, f.y, base));
        }
    }

    float* Srep = g_S8[blockIdx.x & (NREP - 1)];
    #pragma unroll
    for (int q = 0; q < 8; q++)
        atomicAdd(&Srep[j0 + q], acc[q]);

    // term1: threads 0..63 each handle one (b, row) pair; 16-lane segment reduce.
    if (tid < 64) {
        const int b  = tid >> 4;
        const int n  = n0 + (tid & 15);
        float pmv = __ldg(pm + b * N_POSN + n);
        float p   = fminf(fmaxf((pmv - pmin) * invr, 0.0f), 1.0f);
        float rm  = g_rowmin[b * N_POSN + n];
        float t1  = p * rm;
        float ne  = p;
        #pragma unroll
        for (int o = 8; o; o >>= 1) {
            t1 += __shfl_xor_sync(0xFFFFFFFFu, t1, o);
            ne += __shfl_xor_sync(0xFFFFFFFFu, ne, o);
        }
        if ((tid & 15) == 0) {
            atomicAdd(&g_t1[b], t1);
            atomicAdd(&g_ne[b], ne);
        }
    }
}

// ---------------- kernel 3: finalize scalar ----------------
__global__ void __launch_bounds__(512) k_final(float* __restrict__ out) {
    __shared__ float ssum[512];
    const int tid = threadIdx.x;
    float s = 0.0f;
    #pragma unroll
    for (int m = 0; m < NJ / 512; m++) {
        int j = tid + m * 512;
        float S = 0.0f;
        #pragma unroll
        for (int rp = 0; rp < NREP; rp++) S += g_S8[rp][j];
        s += (float)N_POSN / S;
    }
    ssum[tid] = s;
    __syncthreads();
    for (int o = 256; o; o >>= 1) {
        if (tid < o) ssum[tid] += ssum[tid + o];
        __syncthreads();
    }
    if (tid == 0) {
        float term2 = ssum[0] / (float)(NB * NG);
        float term1 = 0.0f;
        #pragma unroll
        for (int b = 0; b < NB; b++)
            term1 += g_t1[b] / (g_ne[b] + EPSF);
        term1 *= (1.0f / NB);
        out[0] = term1 + term2;
    }
}

// ---------------- launch ----------------
extern "C" void kernel_launch(void* const* d_in, const int* in_sizes, int n_in,
                              void* d_out, int out_size) {
    (void)in_sizes; (void)n_in; (void)out_size;
    const float* prob_map = (const float*)d_in[0];   // (4, 8192) f32
    const int*   gt       = (const int*)d_in[1];     // (4, 512)  i32
    const float* dis      = (const float*)d_in[2];   // (8192, 8192) f32
    float* out = (float*)d_out;

    k_gather<<<1024, 256>>>(dis, gt, prob_map);
    k_main<<<N_POSN / B_ROWS, 512>>>(prob_map);
    k_final<<<1, 512>>>(out);
}